// round 3
// baseline (speedup 1.0000x reference)
#include <cuda_runtime.h>
#include <cstdint>

// ---------------------------------------------------------------------------
// MNIST TWN CNN forward, fp32 baseline.
// x[512,1,28,28] -> conv1(64,5x5) -> BN -> relu -> pool2 -> conv2(128,5x5)
// -> BN -> relu -> pool2 -> flatten -> fc1(512) -> BN -> relu -> fc2(10)
// Weights ternary-quantized with threshold 0.05*max|w|.
// ---------------------------------------------------------------------------

#define Bn 512
#define C1 64
#define C2 128
#define F1 512
#define FLAT 2048

// ------------------------- device scratch (no allocs) ----------------------
__device__ float g_q1[C1 * 25];              // quantized conv1 weights
__device__ float g_q2[C2 * C1 * 25];         // quantized conv2 weights
__device__ float g_qf1[F1 * FLAT];           // quantized fc1 weights
__device__ float g_qf2[10 * F1];             // quantized fc2 weights

__device__ float g_c1[(size_t)Bn * C1 * 24 * 24];   // conv1 out   (75.5 MB)
__device__ float g_p1[(size_t)Bn * C1 * 12 * 12];   // pool1 out   (18.9 MB)
__device__ float g_c2[(size_t)Bn * C2 * 8 * 8];     // conv2 out   (16.8 MB)
__device__ float g_p2[(size_t)Bn * FLAT];           // pool2/flat  (4 MB)
__device__ float g_f1[(size_t)Bn * F1];             // fc1 out     (1 MB)

__device__ unsigned g_amax[4];
__device__ double g_sum1[C1], g_ssq1[C1];
__device__ double g_sum2[C2], g_ssq2[C2];
__device__ double g_sum3[F1], g_ssq3[F1];
__device__ float g_sc1[C1], g_sh1[C1];
__device__ float g_sc2[C2], g_sh2[C2];
__device__ float g_sc3[F1], g_sh3[F1];

// ------------------------------ init ---------------------------------------
__global__ void k_init() {
    int t = threadIdx.x;
    if (t < 4) g_amax[t] = 0u;
    for (int i = t; i < C1; i += blockDim.x) { g_sum1[i] = 0.0; g_ssq1[i] = 0.0; }
    for (int i = t; i < C2; i += blockDim.x) { g_sum2[i] = 0.0; g_ssq2[i] = 0.0; }
    for (int i = t; i < F1; i += blockDim.x) { g_sum3[i] = 0.0; g_ssq3[i] = 0.0; }
}

// --------------------------- abs-max reduce --------------------------------
__global__ void k_absmax(const float* __restrict__ src, int n, int slot) {
    __shared__ unsigned red[256];
    unsigned m = 0;
    for (int i = blockIdx.x * blockDim.x + threadIdx.x; i < n;
         i += gridDim.x * blockDim.x) {
        m = max(m, __float_as_uint(fabsf(src[i])));
    }
    red[threadIdx.x] = m;
    __syncthreads();
    for (int o = 128; o > 0; o >>= 1) {
        if (threadIdx.x < o) red[threadIdx.x] = max(red[threadIdx.x], red[threadIdx.x + o]);
        __syncthreads();
    }
    if (threadIdx.x == 0) atomicMax(&g_amax[slot], red[0]);
}

// ----------------------------- quantize ------------------------------------
__device__ __forceinline__ void quant_dev(const float* __restrict__ src,
                                          float* __restrict__ dst, int n, int slot) {
    float t = 0.05f * __uint_as_float(g_amax[slot]);
    for (int i = blockIdx.x * blockDim.x + threadIdx.x; i < n;
         i += gridDim.x * blockDim.x) {
        float w = src[i];
        dst[i] = (w > t ? 1.0f : 0.0f) - (w < -t ? 1.0f : 0.0f);
    }
}
__global__ void k_quant1(const float* __restrict__ s) { quant_dev(s, g_q1, C1 * 25, 0); }
__global__ void k_quant2(const float* __restrict__ s) { quant_dev(s, g_q2, C2 * C1 * 25, 1); }
__global__ void k_quant3(const float* __restrict__ s) { quant_dev(s, g_qf1, F1 * FLAT, 2); }
__global__ void k_quant4(const float* __restrict__ s) { quant_dev(s, g_qf2, 10 * F1, 3); }

// ------------------------------- conv1 -------------------------------------
// Block = 1 batch image. 288 threads, each computes 2 horizontal outputs
// for all 64 channels. x tile + weights in smem.
__global__ void k_conv1(const float* __restrict__ x, const float* __restrict__ bias) {
    __shared__ float xs[28 * 28];
    __shared__ float ws[C1 * 25];
    int b = blockIdx.x, tid = threadIdx.x;
    for (int i = tid; i < 784; i += 288) xs[i] = x[b * 784 + i];
    for (int i = tid; i < C1 * 25; i += 288) ws[i] = g_q1[i];
    __syncthreads();

    int oy = tid / 12;
    int oxp = (tid % 12) * 2;

    float xr[5][6];
#pragma unroll
    for (int r = 0; r < 5; r++)
#pragma unroll
        for (int c = 0; c < 6; c++)
            xr[r][c] = xs[(oy + r) * 28 + oxp + c];

    for (int cb = 0; cb < 4; cb++) {
        float a0[16], a1[16];
#pragma unroll
        for (int j = 0; j < 16; j++) {
            float bb = __ldg(&bias[cb * 16 + j]);
            a0[j] = bb; a1[j] = bb;
        }
#pragma unroll
        for (int j = 0; j < 16; j++) {
            const float* w = &ws[(cb * 16 + j) * 25];
#pragma unroll
            for (int ky = 0; ky < 5; ky++)
#pragma unroll
                for (int kx = 0; kx < 5; kx++) {
                    float wv = w[ky * 5 + kx];
                    a0[j] = fmaf(wv, xr[ky][kx], a0[j]);
                    a1[j] = fmaf(wv, xr[ky][kx + 1], a1[j]);
                }
        }
#pragma unroll
        for (int j = 0; j < 16; j++) {
            int oc = cb * 16 + j;
            size_t base = ((size_t)(b * C1 + oc)) * 576 + oy * 24 + oxp;
            g_c1[base] = a0[j];
            g_c1[base + 1] = a1[j];
        }
    }
}

// ------------------------------ BN stats -----------------------------------
// Layout [B][C][S]; one channel per blockIdx.x, blockIdx.y strides the data.
__device__ __forceinline__ void stats_dev(const float* __restrict__ src,
                                          int Bv, int C, int S,
                                          double* sum, double* ssq) {
    int c = blockIdx.x;
    int total = Bv * S;
    float s = 0.f, q = 0.f;
    for (int i = blockIdx.y * blockDim.x + threadIdx.x; i < total;
         i += gridDim.y * blockDim.x) {
        int b = i / S, sp = i - b * S;
        float v = src[((size_t)b * C + c) * S + sp];
        s += v;
        q += v * v;
    }
    __shared__ float rs[256], rq[256];
    rs[threadIdx.x] = s; rq[threadIdx.x] = q;
    __syncthreads();
    for (int o = 128; o > 0; o >>= 1) {
        if (threadIdx.x < o) {
            rs[threadIdx.x] += rs[threadIdx.x + o];
            rq[threadIdx.x] += rq[threadIdx.x + o];
        }
        __syncthreads();
    }
    if (threadIdx.x == 0) {
        atomicAdd(&sum[c], (double)rs[0]);
        atomicAdd(&ssq[c], (double)rq[0]);
    }
}
__global__ void k_stats1() { stats_dev(g_c1, Bn, C1, 576, g_sum1, g_ssq1); }
__global__ void k_stats2() { stats_dev(g_c2, Bn, C2, 64, g_sum2, g_ssq2); }
__global__ void k_stats3() { stats_dev(g_f1, Bn, F1, 1, g_sum3, g_ssq3); }

// --------------------------- BN finalize -----------------------------------
__device__ __forceinline__ void bnf_dev(int C, double N, const double* sum,
                                        const double* ssq,
                                        const float* __restrict__ gam,
                                        const float* __restrict__ bet,
                                        float* sc, float* sh) {
    int c = blockIdx.x * blockDim.x + threadIdx.x;
    if (c < C) {
        double m = sum[c] / N;
        double v = ssq[c] / N - m * m;
        double a = (double)gam[c] * rsqrt(v + 1e-5);
        sc[c] = (float)a;
        sh[c] = (float)((double)bet[c] - m * a);
    }
}
__global__ void k_bnf1(const float* __restrict__ g, const float* __restrict__ b) {
    bnf_dev(C1, (double)Bn * 576, g_sum1, g_ssq1, g, b, g_sc1, g_sh1);
}
__global__ void k_bnf2(const float* __restrict__ g, const float* __restrict__ b) {
    bnf_dev(C2, (double)Bn * 64, g_sum2, g_ssq2, g, b, g_sc2, g_sh2);
}
__global__ void k_bnf3(const float* __restrict__ g, const float* __restrict__ b) {
    bnf_dev(F1, (double)Bn, g_sum3, g_ssq3, g, b, g_sc3, g_sh3);
}

// --------------------- BN affine + relu + 2x2 maxpool -----------------------
__device__ __forceinline__ void pool_dev(const float* __restrict__ src,
                                         float* __restrict__ dst,
                                         const float* __restrict__ sc,
                                         const float* __restrict__ sh,
                                         int C, int HO, int WO, int total) {
    for (int i = blockIdx.x * blockDim.x + threadIdx.x; i < total;
         i += gridDim.x * blockDim.x) {
        int x = i % WO;
        int y = (i / WO) % HO;
        int c = (i / (WO * HO)) % C;
        int b = i / (WO * HO * C);
        const float* p = src + (((size_t)b * C + c) * (2 * HO) + 2 * y) * (2 * WO) + 2 * x;
        float a = sc[c], s0 = sh[c];
        float r0 = fmaxf(fmaf(a, p[0], s0), fmaf(a, p[1], s0));
        float r1 = fmaxf(fmaf(a, p[2 * WO], s0), fmaf(a, p[2 * WO + 1], s0));
        dst[i] = fmaxf(fmaxf(r0, r1), 0.0f);
    }
}
__global__ void k_pool1() { pool_dev(g_c1, g_p1, g_sc1, g_sh1, C1, 12, 12, Bn * C1 * 144); }
__global__ void k_pool2() { pool_dev(g_c2, g_p2, g_sc2, g_sh2, C2, 4, 4, Bn * C2 * 16); }

// ------------------------------- conv2 -------------------------------------
// Block = 1 batch, 256 threads. Thread (og,sg): 8 output channels x 2x2
// spatial register tile. Input (half the ic's at a time) + per-ic weight
// slice staged in smem. 51200 FMA / thread.
__global__ void __launch_bounds__(256) k_conv2(const float* __restrict__ bias) {
    __shared__ float xs[32 * 144];   // 18.4 KB: 32 input channels of 12x12
    __shared__ float ws[C2 * 25];    // 12.8 KB: all oc for one ic
    int b = blockIdx.x, tid = threadIdx.x;
    int og = tid >> 4, sg = tid & 15;
    int sy = (sg >> 2) * 2, sx = (sg & 3) * 2;
    int ocb = og * 8;

    float acc[8][2][2];
#pragma unroll
    for (int j = 0; j < 8; j++) {
        float bb = __ldg(&bias[ocb + j]);
        acc[j][0][0] = bb; acc[j][0][1] = bb; acc[j][1][0] = bb; acc[j][1][1] = bb;
    }

    for (int h = 0; h < 2; h++) {
        __syncthreads();
        for (int i = tid; i < 32 * 144; i += 256)
            xs[i] = g_p1[((size_t)b * C1 + h * 32) * 144 + i];
        for (int ic = 0; ic < 32; ic++) {
            __syncthreads();
            int icg = h * 32 + ic;
            for (int i = tid; i < C2 * 25; i += 256) {
                int oc = i / 25, k = i - oc * 25;
                ws[i] = g_q2[(oc * C1 + icg) * 25 + k];
            }
            __syncthreads();
            const float* xb = xs + ic * 144;
#pragma unroll
            for (int ky = 0; ky < 5; ky++)
#pragma unroll
                for (int kx = 0; kx < 5; kx++) {
                    float x00 = xb[(sy + ky) * 12 + sx + kx];
                    float x01 = xb[(sy + ky) * 12 + sx + kx + 1];
                    float x10 = xb[(sy + ky + 1) * 12 + sx + kx];
                    float x11 = xb[(sy + ky + 1) * 12 + sx + kx + 1];
#pragma unroll
                    for (int j = 0; j < 8; j++) {
                        float w = ws[(ocb + j) * 25 + ky * 5 + kx];
                        acc[j][0][0] = fmaf(w, x00, acc[j][0][0]);
                        acc[j][0][1] = fmaf(w, x01, acc[j][0][1]);
                        acc[j][1][0] = fmaf(w, x10, acc[j][1][0]);
                        acc[j][1][1] = fmaf(w, x11, acc[j][1][1]);
                    }
                }
        }
    }
#pragma unroll
    for (int j = 0; j < 8; j++)
#pragma unroll
        for (int dy = 0; dy < 2; dy++)
#pragma unroll
            for (int dx = 0; dx < 2; dx++)
                g_c2[((size_t)(b * C2 + ocb + j)) * 64 + (sy + dy) * 8 + (sx + dx)] =
                    acc[j][dy][dx];
}

// -------------------------------- fc1 --------------------------------------
// GEMM: out[512,512] = g_p2[512,2048] @ g_qf1[512,2048]^T + bias
// BM=64 BN=32 BK=32, 128 threads, 4x4 register tile, transposed smem tiles.
#define BM 64
#define BN 32
#define BK 32
__global__ void __launch_bounds__(128) k_fc1(const float* __restrict__ bias) {
    __shared__ __align__(16) float As[BK][BM];
    __shared__ __align__(16) float Wsh[BK][BN];
    int tid = threadIdx.x;
    int tx = tid & 7, ty = tid >> 3;   // tx 0..7 (N), ty 0..15 (M)
    int m0 = blockIdx.y * BM, f0 = blockIdx.x * BN;

    float acc[4][4];
#pragma unroll
    for (int i = 0; i < 4; i++)
#pragma unroll
        for (int j = 0; j < 4; j++) acc[i][j] = 0.f;

    for (int kt = 0; kt < FLAT; kt += BK) {
        __syncthreads();
        for (int i = tid; i < BM * (BK / 4); i += 128) {     // 512 float4
            int r = i >> 3, c4 = (i & 7) * 4;
            float4 v = *(const float4*)&g_p2[(size_t)(m0 + r) * FLAT + kt + c4];
            As[c4 + 0][r] = v.x; As[c4 + 1][r] = v.y;
            As[c4 + 2][r] = v.z; As[c4 + 3][r] = v.w;
        }
        for (int i = tid; i < BN * (BK / 4); i += 128) {     // 256 float4
            int r = i >> 3, c4 = (i & 7) * 4;
            float4 v = *(const float4*)&g_qf1[(size_t)(f0 + r) * FLAT + kt + c4];
            Wsh[c4 + 0][r] = v.x; Wsh[c4 + 1][r] = v.y;
            Wsh[c4 + 2][r] = v.z; Wsh[c4 + 3][r] = v.w;
        }
        __syncthreads();
#pragma unroll
        for (int kk = 0; kk < BK; kk++) {
            float4 av = *(const float4*)&As[kk][ty * 4];
            float4 wv = *(const float4*)&Wsh[kk][tx * 4];
            float a[4] = {av.x, av.y, av.z, av.w};
            float w[4] = {wv.x, wv.y, wv.z, wv.w};
#pragma unroll
            for (int i = 0; i < 4; i++)
#pragma unroll
                for (int j = 0; j < 4; j++)
                    acc[i][j] = fmaf(a[i], w[j], acc[i][j]);
        }
    }
#pragma unroll
    for (int i = 0; i < 4; i++)
#pragma unroll
        for (int j = 0; j < 4; j++) {
            int bb = m0 + ty * 4 + i, f = f0 + tx * 4 + j;
            g_f1[(size_t)bb * F1 + f] = acc[i][j] + __ldg(&bias[f]);
        }
}

// -------------------------------- fc2 --------------------------------------
__global__ void k_fc2(const float* __restrict__ bias, float* __restrict__ out) {
    int i = blockIdx.x * blockDim.x + threadIdx.x;
    if (i >= Bn * 10) return;
    int b = i / 10, j = i - b * 10;
    float s = __ldg(&bias[j]);
    const float* row = &g_f1[(size_t)b * F1];
    const float* w = &g_qf2[(size_t)j * F1];
    for (int f = 0; f < F1; f++) {
        float hh = fmaxf(fmaf(g_sc3[f], row[f], g_sh3[f]), 0.0f);
        s = fmaf(hh, w[f], s);
    }
    out[i] = s;
}

// ------------------------------ launcher -----------------------------------
extern "C" void kernel_launch(void* const* d_in, const int* in_sizes, int n_in,
                              void* d_out, int out_size) {
    const float* x    = (const float*)d_in[0];
    const float* c1w  = (const float*)d_in[1];
    const float* c1b  = (const float*)d_in[2];
    const float* bn1g = (const float*)d_in[3];
    const float* bn1b = (const float*)d_in[4];
    const float* c2w  = (const float*)d_in[5];
    const float* c2b  = (const float*)d_in[6];
    const float* bn2g = (const float*)d_in[7];
    const float* bn2b = (const float*)d_in[8];
    const float* f1w  = (const float*)d_in[9];
    const float* f1b  = (const float*)d_in[10];
    const float* bn3g = (const float*)d_in[11];
    const float* bn3b = (const float*)d_in[12];
    const float* f2w  = (const float*)d_in[13];
    const float* f2b  = (const float*)d_in[14];
    float* out = (float*)d_out;

    k_init<<<1, 1024>>>();

    k_absmax<<<7, 256>>>(c1w, C1 * 25, 0);
    k_absmax<<<800, 256>>>(c2w, C2 * C1 * 25, 1);
    k_absmax<<<2048, 256>>>(f1w, F1 * FLAT, 2);
    k_absmax<<<20, 256>>>(f2w, 10 * F1, 3);

    k_quant1<<<7, 256>>>(c1w);
    k_quant2<<<800, 256>>>(c2w);
    k_quant3<<<4096, 256>>>(f1w);
    k_quant4<<<20, 256>>>(f2w);

    k_conv1<<<512, 288>>>(x, c1b);
    k_stats1<<<dim3(C1, 16), 256>>>();
    k_bnf1<<<1, 64>>>(bn1g, bn1b);
    k_pool1<<<4608, 256>>>();

    k_conv2<<<512, 256>>>(c2b);
    k_stats2<<<dim3(C2, 8), 256>>>();
    k_bnf2<<<1, 128>>>(bn2g, bn2b);
    k_pool2<<<1024, 256>>>();

    k_fc1<<<dim3(F1 / BN, Bn / BM), 128>>>(f1b);
    k_stats3<<<dim3(F1, 1), 256>>>();
    k_bnf3<<<2, 256>>>(bn3g, bn3b);

    k_fc2<<<20, 256>>>(f2b, out);
}

// round 4
// speedup vs baseline: 1.2221x; 1.2221x over previous
#include <cuda_runtime.h>
#include <cstdint>

// ---------------------------------------------------------------------------
// MNIST TWN CNN forward, fp32 + packed f32x2 FMA (FFMA2).
// x[512,1,28,28] -> conv1(64,5x5) -> BN -> relu -> pool2 -> conv2(128,5x5)
// -> BN -> relu -> pool2 -> flatten -> fc1(512) -> BN -> relu -> fc2(10)
// Weights ternary-quantized with threshold 0.05*max|w|.
// ---------------------------------------------------------------------------

#define Bn 512
#define C1 64
#define C2 128
#define F1 512
#define FLAT 2048

typedef unsigned long long u64;

__device__ __forceinline__ u64 pk2(float lo, float hi) {
    u64 r; asm("mov.b64 %0, {%1,%2};" : "=l"(r) : "f"(lo), "f"(hi)); return r;
}
__device__ __forceinline__ u64 f2fma(u64 a, u64 b, u64 c) {
    u64 r; asm("fma.rn.f32x2 %0, %1, %2, %3;" : "=l"(r) : "l"(a), "l"(b), "l"(c));
    return r;
}
__device__ __forceinline__ void upk2(float& lo, float& hi, u64 v) {
    asm("mov.b64 {%0,%1}, %2;" : "=f"(lo), "=f"(hi) : "l"(v));
}

// ------------------------- device scratch (no allocs) ----------------------
__device__ float g_q1t[25 * C1];                 // conv1 weights, [k][oc]
__device__ float g_q2t[C1 * 25 * C2];            // conv2 weights, [ic][k][oc]
__device__ float g_qf1[F1 * FLAT];               // fc1 weights, row-major
__device__ float g_qf2[10 * F1];                 // fc2 weights

__device__ float g_c1[(size_t)Bn * C1 * 24 * 24];   // conv1 out   (75.5 MB)
__device__ float g_p1[(size_t)Bn * C1 * 12 * 12];   // pool1 out   (18.9 MB)
__device__ float g_c2[(size_t)Bn * C2 * 8 * 8];     // conv2 out   (16.8 MB)
__device__ float g_p2[(size_t)Bn * FLAT];           // pool2/flat  (4 MB)
__device__ float g_f1[(size_t)Bn * F1];             // fc1 out     (1 MB)

__device__ unsigned g_amax[4];
__device__ double g_sum1[C1], g_ssq1[C1];
__device__ double g_sum2[C2], g_ssq2[C2];
__device__ double g_sum3[F1], g_ssq3[F1];
__device__ float g_sc1[C1], g_sh1[C1];
__device__ float g_sc2[C2], g_sh2[C2];
__device__ float g_sc3[F1], g_sh3[F1];

// ------------------------------ init ---------------------------------------
__global__ void k_init() {
    int t = threadIdx.x;
    if (t < 4) g_amax[t] = 0u;
    for (int i = t; i < C1; i += blockDim.x) { g_sum1[i] = 0.0; g_ssq1[i] = 0.0; }
    for (int i = t; i < C2; i += blockDim.x) { g_sum2[i] = 0.0; g_ssq2[i] = 0.0; }
    for (int i = t; i < F1; i += blockDim.x) { g_sum3[i] = 0.0; g_ssq3[i] = 0.0; }
}

// --------------------------- abs-max reduce (float4) ------------------------
__global__ void k_absmax(const float* __restrict__ src, int n4, int slot) {
    __shared__ unsigned red[256];
    unsigned m = 0;
    for (int i = blockIdx.x * blockDim.x + threadIdx.x; i < n4;
         i += gridDim.x * blockDim.x) {
        float4 v = *(const float4*)&src[i * 4];
        m = max(m, __float_as_uint(fabsf(v.x)));
        m = max(m, __float_as_uint(fabsf(v.y)));
        m = max(m, __float_as_uint(fabsf(v.z)));
        m = max(m, __float_as_uint(fabsf(v.w)));
    }
    red[threadIdx.x] = m;
    __syncthreads();
    for (int o = 128; o > 0; o >>= 1) {
        if (threadIdx.x < o) red[threadIdx.x] = max(red[threadIdx.x], red[threadIdx.x + o]);
        __syncthreads();
    }
    if (threadIdx.x == 0) atomicMax(&g_amax[slot], red[0]);
}

// ----------------------------- quantize ------------------------------------
__device__ __forceinline__ float tern(float w, float t) {
    return (w > t ? 1.0f : 0.0f) - (w < -t ? 1.0f : 0.0f);
}
// conv1: src [oc][25] -> dst [k][64]
__global__ void k_quant1t(const float* __restrict__ s) {
    float t = 0.05f * __uint_as_float(g_amax[0]);
    int i = blockIdx.x * blockDim.x + threadIdx.x;
    if (i < C1 * 25) {
        int oc = i / 25, k = i - oc * 25;
        g_q1t[k * C1 + oc] = tern(s[i], t);
    }
}
// conv2: src [oc][ic][25] -> dst [ic][k][128]
__global__ void k_quant2t(const float* __restrict__ s) {
    float t = 0.05f * __uint_as_float(g_amax[1]);
    int i = blockIdx.x * blockDim.x + threadIdx.x;
    if (i < C2 * C1 * 25) {
        int oc = i / (C1 * 25), rem = i - oc * C1 * 25;
        int ic = rem / 25, k = rem - ic * 25;
        g_q2t[(ic * 25 + k) * C2 + oc] = tern(s[i], t);
    }
}
__global__ void k_quant3(const float* __restrict__ s) {
    float t = 0.05f * __uint_as_float(g_amax[2]);
    for (int i = blockIdx.x * blockDim.x + threadIdx.x; i < F1 * FLAT;
         i += gridDim.x * blockDim.x)
        g_qf1[i] = tern(s[i], t);
}
__global__ void k_quant4(const float* __restrict__ s) {
    float t = 0.05f * __uint_as_float(g_amax[3]);
    int i = blockIdx.x * blockDim.x + threadIdx.x;
    if (i < 10 * F1) g_qf2[i] = tern(s[i], t);
}

// ------------------------------- conv1 -------------------------------------
// Block = 1 image, 288 threads, each thread: 2 horizontal outputs x 64 oc.
// oc packed in pairs (f32x2). Weights in smem as [k][64].
__global__ void k_conv1(const float* __restrict__ x, const float* __restrict__ bias) {
    __shared__ float xs[28 * 28];
    __shared__ __align__(8) float ws[25 * C1];
    int b = blockIdx.x, tid = threadIdx.x;
    for (int i = tid; i < 784; i += 288) xs[i] = x[b * 784 + i];
    for (int i = tid; i < 25 * C1; i += 288) ws[i] = g_q1t[i];
    __syncthreads();

    int oy = tid / 12;
    int oxp = (tid % 12) * 2;

    float xr[5][6];
#pragma unroll
    for (int r = 0; r < 5; r++)
#pragma unroll
        for (int c = 0; c < 6; c++)
            xr[r][c] = xs[(oy + r) * 28 + oxp + c];

    for (int cb = 0; cb < 4; cb++) {
        u64 a0[8], a1[8];
#pragma unroll
        for (int p = 0; p < 8; p++) {
            u64 bb = pk2(__ldg(&bias[cb * 16 + 2 * p]), __ldg(&bias[cb * 16 + 2 * p + 1]));
            a0[p] = bb; a1[p] = bb;
        }
#pragma unroll
        for (int ky = 0; ky < 5; ky++)
#pragma unroll
            for (int kx = 0; kx < 5; kx++) {
                float x0 = xr[ky][kx], x1 = xr[ky][kx + 1];
                u64 px0 = pk2(x0, x0), px1 = pk2(x1, x1);
                const u64* wp = (const u64*)&ws[(ky * 5 + kx) * C1 + cb * 16];
#pragma unroll
                for (int p = 0; p < 8; p++) {
                    u64 w = wp[p];
                    a0[p] = f2fma(w, px0, a0[p]);
                    a1[p] = f2fma(w, px1, a1[p]);
                }
            }
#pragma unroll
        for (int p = 0; p < 8; p++) {
            float l0, h0, l1, h1;
            upk2(l0, h0, a0[p]);
            upk2(l1, h1, a1[p]);
            int oc = cb * 16 + 2 * p;
            size_t base = ((size_t)(b * C1 + oc)) * 576 + oy * 24 + oxp;
            *(float2*)&g_c1[base]       = make_float2(l0, l1);
            *(float2*)&g_c1[base + 576] = make_float2(h0, h1);
        }
    }
}

// ------------------------------ BN stats -----------------------------------
// float4 variant (S % 4 == 0). Layout [B][C][S], one channel per blockIdx.x.
__device__ __forceinline__ void stats4_dev(const float* __restrict__ src,
                                           int Bv, int C, int S,
                                           double* sum, double* ssq) {
    int c = blockIdx.x;
    int S4 = S >> 2;
    int total = Bv * S4;
    float s = 0.f, q = 0.f;
    for (int i = blockIdx.y * blockDim.x + threadIdx.x; i < total;
         i += gridDim.y * blockDim.x) {
        int b = i / S4, sp = i - b * S4;
        float4 v = *(const float4*)&src[((size_t)b * C + c) * S + sp * 4];
        s += v.x + v.y + v.z + v.w;
        q += v.x * v.x + v.y * v.y + v.z * v.z + v.w * v.w;
    }
    __shared__ float rs[256], rq[256];
    rs[threadIdx.x] = s; rq[threadIdx.x] = q;
    __syncthreads();
    for (int o = 128; o > 0; o >>= 1) {
        if (threadIdx.x < o) {
            rs[threadIdx.x] += rs[threadIdx.x + o];
            rq[threadIdx.x] += rq[threadIdx.x + o];
        }
        __syncthreads();
    }
    if (threadIdx.x == 0) {
        atomicAdd(&sum[c], (double)rs[0]);
        atomicAdd(&ssq[c], (double)rq[0]);
    }
}
__global__ void k_stats1() { stats4_dev(g_c1, Bn, C1, 576, g_sum1, g_ssq1); }
__global__ void k_stats2() { stats4_dev(g_c2, Bn, C2, 64, g_sum2, g_ssq2); }
// fc1 out: [B][F1], per-feature over batch (strided; tiny 1MB).
__global__ void k_stats3() {
    int c = blockIdx.x;
    float s = 0.f, q = 0.f;
    for (int b = threadIdx.x; b < Bn; b += blockDim.x) {
        float v = g_f1[(size_t)b * F1 + c];
        s += v; q += v * v;
    }
    __shared__ float rs[256], rq[256];
    rs[threadIdx.x] = s; rq[threadIdx.x] = q;
    __syncthreads();
    for (int o = 128; o > 0; o >>= 1) {
        if (threadIdx.x < o) {
            rs[threadIdx.x] += rs[threadIdx.x + o];
            rq[threadIdx.x] += rq[threadIdx.x + o];
        }
        __syncthreads();
    }
    if (threadIdx.x == 0) {
        atomicAdd(&g_sum3[c], (double)rs[0]);
        atomicAdd(&g_ssq3[c], (double)rq[0]);
    }
}

// --------------------------- BN finalize -----------------------------------
__device__ __forceinline__ void bnf_dev(int C, double N, const double* sum,
                                        const double* ssq,
                                        const float* __restrict__ gam,
                                        const float* __restrict__ bet,
                                        float* sc, float* sh) {
    int c = blockIdx.x * blockDim.x + threadIdx.x;
    if (c < C) {
        double m = sum[c] / N;
        double v = ssq[c] / N - m * m;
        double a = (double)gam[c] * rsqrt(v + 1e-5);
        sc[c] = (float)a;
        sh[c] = (float)((double)bet[c] - m * a);
    }
}
__global__ void k_bnf1(const float* __restrict__ g, const float* __restrict__ b) {
    bnf_dev(C1, (double)Bn * 576, g_sum1, g_ssq1, g, b, g_sc1, g_sh1);
}
__global__ void k_bnf2(const float* __restrict__ g, const float* __restrict__ b) {
    bnf_dev(C2, (double)Bn * 64, g_sum2, g_ssq2, g, b, g_sc2, g_sh2);
}
__global__ void k_bnf3(const float* __restrict__ g, const float* __restrict__ b) {
    bnf_dev(F1, (double)Bn, g_sum3, g_ssq3, g, b, g_sc3, g_sh3);
}

// --------------------- BN affine + relu + 2x2 maxpool -----------------------
__device__ __forceinline__ void pool_dev(const float* __restrict__ src,
                                         float* __restrict__ dst,
                                         const float* __restrict__ sc,
                                         const float* __restrict__ sh,
                                         int C, int HO, int WO, int total) {
    for (int i = blockIdx.x * blockDim.x + threadIdx.x; i < total;
         i += gridDim.x * blockDim.x) {
        int x = i % WO;
        int y = (i / WO) % HO;
        int c = (i / (WO * HO)) % C;
        int b = i / (WO * HO * C);
        const float* p = src + (((size_t)b * C + c) * (2 * HO) + 2 * y) * (2 * WO) + 2 * x;
        float2 t0 = *(const float2*)p;
        float2 t1 = *(const float2*)(p + 2 * WO);
        float a = sc[c], s0 = sh[c];
        float r0 = fmaxf(fmaf(a, t0.x, s0), fmaf(a, t0.y, s0));
        float r1 = fmaxf(fmaf(a, t1.x, s0), fmaf(a, t1.y, s0));
        dst[i] = fmaxf(fmaxf(r0, r1), 0.0f);
    }
}
__global__ void k_pool1() { pool_dev(g_c1, g_p1, g_sc1, g_sh1, C1, 12, 12, Bn * C1 * 144); }
__global__ void k_pool2() { pool_dev(g_c2, g_p2, g_sc2, g_sh2, C2, 4, 4, Bn * C2 * 16); }

// ------------------------------- conv2 -------------------------------------
// Block = 1 image, 256 threads. Thread (og,sg): 8 oc (4 f32x2 pairs) x
// 2x2 spatial. Weights staged per-ic as [k][128] (oc-contiguous -> LDS.64
// pairs, broadcast across sg). Input 6x6 patch register-cached per ic.
__global__ void __launch_bounds__(256) k_conv2(const float* __restrict__ bias) {
    __shared__ float xs[32 * 144];              // 18.4 KB: 32 ic of 12x12
    __shared__ __align__(8) float ws[25 * C2];  // 12.8 KB: [k][oc] for one ic
    int b = blockIdx.x, tid = threadIdx.x;
    int og = tid >> 4, sg = tid & 15;
    int sy = (sg >> 2) * 2, sx = (sg & 3) * 2;
    int ocb = og * 8;

    u64 acc[4][2][2];
#pragma unroll
    for (int p = 0; p < 4; p++) {
        u64 bb = pk2(__ldg(&bias[ocb + 2 * p]), __ldg(&bias[ocb + 2 * p + 1]));
        acc[p][0][0] = bb; acc[p][0][1] = bb; acc[p][1][0] = bb; acc[p][1][1] = bb;
    }

    for (int h = 0; h < 2; h++) {
        __syncthreads();
        for (int i = tid; i < 32 * 144; i += 256)
            xs[i] = g_p1[((size_t)b * C1 + h * 32) * 144 + i];
        for (int ic = 0; ic < 32; ic++) {
            __syncthreads();
            int icg = h * 32 + ic;
            for (int i = tid; i < 25 * C2; i += 256)
                ws[i] = g_q2t[(size_t)icg * 25 * C2 + i];
            __syncthreads();

            const float* xb = xs + ic * 144;
            float xr[6][6];
#pragma unroll
            for (int r = 0; r < 6; r++)
#pragma unroll
                for (int c = 0; c < 6; c++)
                    xr[r][c] = xb[(sy + r) * 12 + sx + c];

#pragma unroll
            for (int ky = 0; ky < 5; ky++)
#pragma unroll
                for (int kx = 0; kx < 5; kx++) {
                    u64 p00 = pk2(xr[ky][kx],     xr[ky][kx]);
                    u64 p01 = pk2(xr[ky][kx + 1], xr[ky][kx + 1]);
                    u64 p10 = pk2(xr[ky + 1][kx],     xr[ky + 1][kx]);
                    u64 p11 = pk2(xr[ky + 1][kx + 1], xr[ky + 1][kx + 1]);
                    const u64* wp = (const u64*)&ws[(ky * 5 + kx) * C2 + ocb];
#pragma unroll
                    for (int p = 0; p < 4; p++) {
                        u64 w = wp[p];
                        acc[p][0][0] = f2fma(w, p00, acc[p][0][0]);
                        acc[p][0][1] = f2fma(w, p01, acc[p][0][1]);
                        acc[p][1][0] = f2fma(w, p10, acc[p][1][0]);
                        acc[p][1][1] = f2fma(w, p11, acc[p][1][1]);
                    }
                }
        }
    }
#pragma unroll
    for (int p = 0; p < 4; p++)
#pragma unroll
        for (int dy = 0; dy < 2; dy++)
#pragma unroll
            for (int dx = 0; dx < 2; dx++) {
                float lo, hi;
                upk2(lo, hi, acc[p][dy][dx]);
                int oc = ocb + 2 * p;
                size_t base = ((size_t)(b * C2 + oc)) * 64 + (sy + dy) * 8 + (sx + dx);
                g_c2[base] = lo;
                g_c2[base + 64] = hi;
            }
}

// -------------------------------- fc1 --------------------------------------
// GEMM: out[512,512] = g_p2[512,2048] @ g_qf1[512,2048]^T + bias
// BM=64 BN=32 BK=32, 128 threads, 4M x 4N tile, N packed in f32x2 pairs.
#define BM 64
#define BN 32
#define BK 32
__global__ void __launch_bounds__(128) k_fc1(const float* __restrict__ bias) {
    __shared__ __align__(16) float As[BK][BM];
    __shared__ __align__(16) float Wsh[BK][BN];
    int tid = threadIdx.x;
    int tx = tid & 7, ty = tid >> 3;   // tx 0..7 (N), ty 0..15 (M)
    int m0 = blockIdx.y * BM, f0 = blockIdx.x * BN;

    u64 acc[4][2];
#pragma unroll
    for (int i = 0; i < 4; i++) { acc[i][0] = 0ull; acc[i][1] = 0ull; }

    for (int kt = 0; kt < FLAT; kt += BK) {
        __syncthreads();
        for (int i = tid; i < BM * (BK / 4); i += 128) {
            int r = i >> 3, c4 = (i & 7) * 4;
            float4 v = *(const float4*)&g_p2[(size_t)(m0 + r) * FLAT + kt + c4];
            As[c4 + 0][r] = v.x; As[c4 + 1][r] = v.y;
            As[c4 + 2][r] = v.z; As[c4 + 3][r] = v.w;
        }
        for (int i = tid; i < BN * (BK / 4); i += 128) {
            int r = i >> 3, c4 = (i & 7) * 4;
            float4 v = *(const float4*)&g_qf1[(size_t)(f0 + r) * FLAT + kt + c4];
            Wsh[c4 + 0][r] = v.x; Wsh[c4 + 1][r] = v.y;
            Wsh[c4 + 2][r] = v.z; Wsh[c4 + 3][r] = v.w;
        }
        __syncthreads();
#pragma unroll
        for (int kk = 0; kk < BK; kk++) {
            float4 av = *(const float4*)&As[kk][ty * 4];
            u64 w0 = *(const u64*)&Wsh[kk][tx * 4];
            u64 w1 = *(const u64*)&Wsh[kk][tx * 4 + 2];
            float a[4] = {av.x, av.y, av.z, av.w};
#pragma unroll
            for (int i = 0; i < 4; i++) {
                u64 pa = pk2(a[i], a[i]);
                acc[i][0] = f2fma(pa, w0, acc[i][0]);
                acc[i][1] = f2fma(pa, w1, acc[i][1]);
            }
        }
    }
#pragma unroll
    for (int i = 0; i < 4; i++)
#pragma unroll
        for (int jp = 0; jp < 2; jp++) {
            float lo, hi;
            upk2(lo, hi, acc[i][jp]);
            int bb = m0 + ty * 4 + i, f = f0 + tx * 4 + 2 * jp;
            g_f1[(size_t)bb * F1 + f]     = lo + __ldg(&bias[f]);
            g_f1[(size_t)bb * F1 + f + 1] = hi + __ldg(&bias[f + 1]);
        }
}

// -------------------------------- fc2 --------------------------------------
__global__ void k_fc2(const float* __restrict__ bias, float* __restrict__ out) {
    int i = blockIdx.x * blockDim.x + threadIdx.x;
    if (i >= Bn * 10) return;
    int b = i / 10, j = i - b * 10;
    float s = __ldg(&bias[j]);
    const float* row = &g_f1[(size_t)b * F1];
    const float* w = &g_qf2[(size_t)j * F1];
    for (int f = 0; f < F1; f++) {
        float hh = fmaxf(fmaf(g_sc3[f], row[f], g_sh3[f]), 0.0f);
        s = fmaf(hh, w[f], s);
    }
    out[i] = s;
}

// ------------------------------ launcher -----------------------------------
extern "C" void kernel_launch(void* const* d_in, const int* in_sizes, int n_in,
                              void* d_out, int out_size) {
    const float* x    = (const float*)d_in[0];
    const float* c1w  = (const float*)d_in[1];
    const float* c1b  = (const float*)d_in[2];
    const float* bn1g = (const float*)d_in[3];
    const float* bn1b = (const float*)d_in[4];
    const float* c2w  = (const float*)d_in[5];
    const float* c2b  = (const float*)d_in[6];
    const float* bn2g = (const float*)d_in[7];
    const float* bn2b = (const float*)d_in[8];
    const float* f1w  = (const float*)d_in[9];
    const float* f1b  = (const float*)d_in[10];
    const float* bn3g = (const float*)d_in[11];
    const float* bn3b = (const float*)d_in[12];
    const float* f2w  = (const float*)d_in[13];
    const float* f2b  = (const float*)d_in[14];
    float* out = (float*)d_out;

    k_init<<<1, 1024>>>();

    k_absmax<<<2, 256>>>(c1w, C1 * 25 / 4, 0);
    k_absmax<<<200, 256>>>(c2w, C2 * C1 * 25 / 4, 1);
    k_absmax<<<1024, 256>>>(f1w, F1 * FLAT / 4, 2);
    k_absmax<<<5, 256>>>(f2w, 10 * F1 / 4, 3);

    k_quant1t<<<(C1 * 25 + 255) / 256, 256>>>(c1w);
    k_quant2t<<<(C2 * C1 * 25 + 255) / 256, 256>>>(c2w);
    k_quant3<<<2048, 256>>>(f1w);
    k_quant4<<<20, 256>>>(f2w);

    k_conv1<<<512, 288>>>(x, c1b);
    k_stats1<<<dim3(C1, 16), 256>>>();
    k_bnf1<<<1, 64>>>(bn1g, bn1b);
    k_pool1<<<4608, 256>>>();

    k_conv2<<<512, 256>>>(c2b);
    k_stats2<<<dim3(C2, 8), 256>>>();
    k_bnf2<<<1, 128>>>(bn2g, bn2b);
    k_pool2<<<1024, 256>>>();

    k_fc1<<<dim3(F1 / BN, Bn / BM), 128>>>(f1b);
    k_stats3<<<F1, 256>>>();
    k_bnf3<<<2, 256>>>(bn3g, bn3b);

    k_fc2<<<20, 256>>>(f2b, out);
}

// round 5
// speedup vs baseline: 1.5020x; 1.2291x over previous
#include <cuda_runtime.h>
#include <cuda_fp16.h>
#include <cstdint>

// ---------------------------------------------------------------------------
// MNIST TWN CNN forward.
// conv1: scalar f32x2 FMA.  conv2: tensor-core mma.sync f16 (hi/lo split,
// fp32-exact) as 25 shifted NHWC GEMMs.  fc1: f32x2 GEMM.
// ---------------------------------------------------------------------------

#define Bn 512
#define C1 64
#define C2 128
#define F1 512
#define FLAT 2048

typedef unsigned long long u64;

__device__ __forceinline__ u64 pk2(float lo, float hi) {
    u64 r; asm("mov.b64 %0, {%1,%2};" : "=l"(r) : "f"(lo), "f"(hi)); return r;
}
__device__ __forceinline__ u64 f2fma(u64 a, u64 b, u64 c) {
    u64 r; asm("fma.rn.f32x2 %0, %1, %2, %3;" : "=l"(r) : "l"(a), "l"(b), "l"(c));
    return r;
}
__device__ __forceinline__ void upk2(float& lo, float& hi, u64 v) {
    asm("mov.b64 {%0,%1}, %2;" : "=f"(lo), "=f"(hi) : "l"(v));
}

// ------------------------- device scratch (no allocs) ----------------------
__device__ float g_q1t[25 * C1];                    // conv1 weights [k][oc]
__device__ __half g_q2b[25 * C2 * 64];              // conv2 weights [k][oc][ic] f16
__device__ float g_qf1[F1 * FLAT];                  // fc1 weights
__device__ float g_qf2[10 * F1];                    // fc2 weights

__device__ float g_c1[(size_t)Bn * C1 * 24 * 24];   // conv1 out NCHW (75.5 MB)
__device__ __half g_p1h[(size_t)Bn * 144 * 128];    // pool1 NHWC f16 hi/lo (18.9 MB)
__device__ float g_c2n[(size_t)Bn * 64 * C2];       // conv2 out NHWC (16.8 MB)
__device__ float g_p2[(size_t)Bn * FLAT];           // pool2/flat NCHW-flat (4 MB)
__device__ float g_f1[(size_t)Bn * F1];             // fc1 out (1 MB)

__device__ unsigned g_amax[4];
__device__ double g_sum1[C1], g_ssq1[C1];
__device__ double g_sum2[C2], g_ssq2[C2];
__device__ double g_sum3[F1], g_ssq3[F1];
__device__ float g_sc1[C1], g_sh1[C1];
__device__ float g_sc2[C2], g_sh2[C2];
__device__ float g_sc3[F1], g_sh3[F1];

// ------------------------------ init ---------------------------------------
__global__ void k_init() {
    int t = threadIdx.x;
    if (t < 4) g_amax[t] = 0u;
    for (int i = t; i < C1; i += blockDim.x) { g_sum1[i] = 0.0; g_ssq1[i] = 0.0; }
    for (int i = t; i < C2; i += blockDim.x) { g_sum2[i] = 0.0; g_ssq2[i] = 0.0; }
    for (int i = t; i < F1; i += blockDim.x) { g_sum3[i] = 0.0; g_ssq3[i] = 0.0; }
}

// --------------------------- abs-max reduce (float4) ------------------------
__global__ void k_absmax(const float* __restrict__ src, int n4, int slot) {
    __shared__ unsigned red[256];
    unsigned m = 0;
    for (int i = blockIdx.x * blockDim.x + threadIdx.x; i < n4;
         i += gridDim.x * blockDim.x) {
        float4 v = *(const float4*)&src[i * 4];
        m = max(m, __float_as_uint(fabsf(v.x)));
        m = max(m, __float_as_uint(fabsf(v.y)));
        m = max(m, __float_as_uint(fabsf(v.z)));
        m = max(m, __float_as_uint(fabsf(v.w)));
    }
    red[threadIdx.x] = m;
    __syncthreads();
    for (int o = 128; o > 0; o >>= 1) {
        if (threadIdx.x < o) red[threadIdx.x] = max(red[threadIdx.x], red[threadIdx.x + o]);
        __syncthreads();
    }
    if (threadIdx.x == 0) atomicMax(&g_amax[slot], red[0]);
}

// ----------------------------- quantize ------------------------------------
__device__ __forceinline__ float tern(float w, float t) {
    return (w > t ? 1.0f : 0.0f) - (w < -t ? 1.0f : 0.0f);
}
__global__ void k_quant1t(const float* __restrict__ s) {
    float t = 0.05f * __uint_as_float(g_amax[0]);
    int i = blockIdx.x * blockDim.x + threadIdx.x;
    if (i < C1 * 25) {
        int oc = i / 25, k = i - oc * 25;
        g_q1t[k * C1 + oc] = tern(s[i], t);
    }
}
// conv2: src [oc][ic][25] -> [k][oc][ic] f16
__global__ void k_quant2b(const float* __restrict__ s) {
    float t = 0.05f * __uint_as_float(g_amax[1]);
    int i = blockIdx.x * blockDim.x + threadIdx.x;
    if (i < C2 * C1 * 25) {
        int oc = i / (C1 * 25), rem = i - oc * C1 * 25;
        int ic = rem / 25, kk = rem - ic * 25;
        g_q2b[(kk * C2 + oc) * 64 + ic] = __float2half(tern(s[i], t));
    }
}
__global__ void k_quant3(const float* __restrict__ s) {
    float t = 0.05f * __uint_as_float(g_amax[2]);
    for (int i = blockIdx.x * blockDim.x + threadIdx.x; i < F1 * FLAT;
         i += gridDim.x * blockDim.x)
        g_qf1[i] = tern(s[i], t);
}
__global__ void k_quant4(const float* __restrict__ s) {
    float t = 0.05f * __uint_as_float(g_amax[3]);
    int i = blockIdx.x * blockDim.x + threadIdx.x;
    if (i < 10 * F1) g_qf2[i] = tern(s[i], t);
}

// ------------------------------- conv1 (f32x2) ------------------------------
__global__ void k_conv1(const float* __restrict__ x, const float* __restrict__ bias) {
    __shared__ float xs[28 * 28];
    __shared__ __align__(8) float ws[25 * C1];
    int b = blockIdx.x, tid = threadIdx.x;
    for (int i = tid; i < 784; i += 288) xs[i] = x[b * 784 + i];
    for (int i = tid; i < 25 * C1; i += 288) ws[i] = g_q1t[i];
    __syncthreads();

    int oy = tid / 12;
    int oxp = (tid % 12) * 2;

    float xr[5][6];
#pragma unroll
    for (int r = 0; r < 5; r++)
#pragma unroll
        for (int c = 0; c < 6; c++)
            xr[r][c] = xs[(oy + r) * 28 + oxp + c];

    for (int cb = 0; cb < 4; cb++) {
        u64 a0[8], a1[8];
#pragma unroll
        for (int p = 0; p < 8; p++) {
            u64 bb = pk2(__ldg(&bias[cb * 16 + 2 * p]), __ldg(&bias[cb * 16 + 2 * p + 1]));
            a0[p] = bb; a1[p] = bb;
        }
#pragma unroll
        for (int ky = 0; ky < 5; ky++)
#pragma unroll
            for (int kx = 0; kx < 5; kx++) {
                float x0 = xr[ky][kx], x1 = xr[ky][kx + 1];
                u64 px0 = pk2(x0, x0), px1 = pk2(x1, x1);
                const u64* wp = (const u64*)&ws[(ky * 5 + kx) * C1 + cb * 16];
#pragma unroll
                for (int p = 0; p < 8; p++) {
                    u64 w = wp[p];
                    a0[p] = f2fma(w, px0, a0[p]);
                    a1[p] = f2fma(w, px1, a1[p]);
                }
            }
#pragma unroll
        for (int p = 0; p < 8; p++) {
            float l0, h0, l1, h1;
            upk2(l0, h0, a0[p]);
            upk2(l1, h1, a1[p]);
            int oc = cb * 16 + 2 * p;
            size_t base = ((size_t)(b * C1 + oc)) * 576 + oy * 24 + oxp;
            *(float2*)&g_c1[base]       = make_float2(l0, l1);
            *(float2*)&g_c1[base + 576] = make_float2(h0, h1);
        }
    }
}

// ------------------------------ BN stats (conv1) ----------------------------
__global__ void k_stats1() {
    int c = blockIdx.x;
    int total = Bn * 144;  // 576/4
    float s = 0.f, q = 0.f;
    for (int i = blockIdx.y * blockDim.x + threadIdx.x; i < total;
         i += gridDim.y * blockDim.x) {
        int b = i / 144, sp = i - b * 144;
        float4 v = *(const float4*)&g_c1[((size_t)b * C1 + c) * 576 + sp * 4];
        s += v.x + v.y + v.z + v.w;
        q += v.x * v.x + v.y * v.y + v.z * v.z + v.w * v.w;
    }
    __shared__ float rs[256], rq[256];
    rs[threadIdx.x] = s; rq[threadIdx.x] = q;
    __syncthreads();
    for (int o = 128; o > 0; o >>= 1) {
        if (threadIdx.x < o) {
            rs[threadIdx.x] += rs[threadIdx.x + o];
            rq[threadIdx.x] += rq[threadIdx.x + o];
        }
        __syncthreads();
    }
    if (threadIdx.x == 0) {
        atomicAdd(&g_sum1[c], (double)rs[0]);
        atomicAdd(&g_ssq1[c], (double)rq[0]);
    }
}

// conv2 out NHWC: per-oc sums, coalesced rows.
__global__ void k_stats2n() {
    int oc = threadIdx.x;  // 128
    float s = 0.f, q = 0.f;
    for (int r = blockIdx.x; r < Bn * 64; r += gridDim.x) {
        float v = g_c2n[(size_t)r * 128 + oc];
        s += v; q += v * v;
    }
    atomicAdd(&g_sum2[oc], (double)s);
    atomicAdd(&g_ssq2[oc], (double)q);
}

__global__ void k_stats3() {
    int c = blockIdx.x;
    float s = 0.f, q = 0.f;
    for (int b = threadIdx.x; b < Bn; b += blockDim.x) {
        float v = g_f1[(size_t)b * F1 + c];
        s += v; q += v * v;
    }
    __shared__ float rs[256], rq[256];
    rs[threadIdx.x] = s; rq[threadIdx.x] = q;
    __syncthreads();
    for (int o = 128; o > 0; o >>= 1) {
        if (threadIdx.x < o) {
            rs[threadIdx.x] += rs[threadIdx.x + o];
            rq[threadIdx.x] += rq[threadIdx.x + o];
        }
        __syncthreads();
    }
    if (threadIdx.x == 0) {
        atomicAdd(&g_sum3[c], (double)rs[0]);
        atomicAdd(&g_ssq3[c], (double)rq[0]);
    }
}

// --------------------------- BN finalize -----------------------------------
__device__ __forceinline__ void bnf_dev(int C, double N, const double* sum,
                                        const double* ssq,
                                        const float* __restrict__ gam,
                                        const float* __restrict__ bet,
                                        float* sc, float* sh) {
    int c = blockIdx.x * blockDim.x + threadIdx.x;
    if (c < C) {
        double m = sum[c] / N;
        double v = ssq[c] / N - m * m;
        double a = (double)gam[c] * rsqrt(v + 1e-5);
        sc[c] = (float)a;
        sh[c] = (float)((double)bet[c] - m * a);
    }
}
__global__ void k_bnf1(const float* __restrict__ g, const float* __restrict__ b) {
    bnf_dev(C1, (double)Bn * 576, g_sum1, g_ssq1, g, b, g_sc1, g_sh1);
}
__global__ void k_bnf2(const float* __restrict__ g, const float* __restrict__ b) {
    bnf_dev(C2, (double)Bn * 64, g_sum2, g_ssq2, g, b, g_sc2, g_sh2);
}
__global__ void k_bnf3(const float* __restrict__ g, const float* __restrict__ b) {
    bnf_dev(F1, (double)Bn, g_sum3, g_ssq3, g, b, g_sc3, g_sh3);
}

// ------- pool1: BN+relu+2x2max, NCHW fp32 -> NHWC f16 hi/lo (transpose) ------
__global__ void __launch_bounds__(256) k_pool1h() {
    __shared__ float smt[144 * 65];   // [s][c], pad 65 for bank-conflict-free
    int b = blockIdx.x, tid = threadIdx.x;
    for (int i = tid; i < 64 * 144; i += 256) {
        int c = i / 144, s = i - c * 144;
        int y = s / 12, x = s - y * 12;
        const float* p = &g_c1[((size_t)(b * 64 + c)) * 576 + (2 * y) * 24 + 2 * x];
        float2 t0 = *(const float2*)p;
        float2 t1 = *(const float2*)(p + 24);
        float a = g_sc1[c], sh = g_sh1[c];
        float r0 = fmaxf(fmaf(a, t0.x, sh), fmaf(a, t0.y, sh));
        float r1 = fmaxf(fmaf(a, t1.x, sh), fmaf(a, t1.y, sh));
        smt[s * 65 + c] = fmaxf(fmaxf(r0, r1), 0.0f);
    }
    __syncthreads();
    for (int i = tid; i < 144 * 128; i += 256) {
        int s = i >> 7, cc = i & 127;
        float v = smt[s * 65 + (cc & 63)];
        __half hi = __float2half(v);
        __half h = (cc < 64) ? hi : __float2half(v - __half2float(hi));
        g_p1h[((size_t)b * 144 + s) * 128 + cc] = h;
    }
}

// ----------------------- conv2: tensor-core mma.sync ------------------------
// CTA = 2 images, 256 threads (8 warps). Warp tile M32 x N64 (2 m-tiles x
// 8 n-tiles of m16n8k16). 25 shifted GEMMs over (ky,kx), K=128 slots
// (hi 0-63 | lo 64-127, B tile reused for both halves). B double-buffered.
#define CV2_XBYTES (288 * 272)
#define CV2_BBYTES 16384
#define CV2_SMEM (CV2_XBYTES + 2 * CV2_BBYTES)

__global__ void __launch_bounds__(256, 2) k_conv2m(const float* __restrict__ bias) {
    extern __shared__ char sm[];
    char* Xs = sm;                    // 288 rows x 272B (256B data + 16B pad)
    char* Bsm = sm + CV2_XBYTES;      // 2 x 16KB, XOR-swizzled 16B chunks
    const int tid = threadIdx.x;
    const int lane = tid & 31, w = tid >> 5;
    const int g = lane >> 2, t = lane & 3;
    const int blk = blockIdx.x;

    // stage X (both images): 4608 16B chunks
    const char* xsrc = (const char*)g_p1h + (size_t)blk * 288 * 256;
    for (int i = tid; i < 4608; i += 256) {
        int row = i >> 4, ch = i & 15;
        *(uint4*)(Xs + row * 272 + ch * 16) =
            *(const uint4*)(xsrc + row * 256 + ch * 16);
    }
    // stage B(kk=0) into buffer 0
    {
        const char* bsrc = (const char*)g_q2b;
#pragma unroll
        for (int j = 0; j < 4; j++) {
            int i = tid + j * 256;
            int row = i >> 3, ch = i & 7;
            *(uint4*)(Bsm + row * 128 + ((ch ^ (row & 7)) << 4)) =
                *(const uint4*)(bsrc + row * 128 + ch * 16);
        }
    }

    const int m0w = (w >> 1) * 32;
    const int n0w = (w & 1) * 64;

    // A-fragment base byte addresses (rows g, g+8 per m-tile)
    int abase[2][2];
#pragma unroll
    for (int mt = 0; mt < 2; mt++)
#pragma unroll
        for (int rr = 0; rr < 2; rr++) {
            int m = m0w + mt * 16 + g + rr * 8;
            int img = m >> 6, sp = m & 63;
            int xrow = img * 144 + (sp >> 3) * 12 + (sp & 7);
            abase[mt][rr] = xrow * 272 + 4 * t;
        }

    float acc[2][8][4];
#pragma unroll
    for (int nt = 0; nt < 8; nt++) {
        float b0v = __ldg(&bias[n0w + nt * 8 + 2 * t]);
        float b1v = __ldg(&bias[n0w + nt * 8 + 2 * t + 1]);
#pragma unroll
        for (int mt = 0; mt < 2; mt++) {
            acc[mt][nt][0] = b0v; acc[mt][nt][1] = b1v;
            acc[mt][nt][2] = b0v; acc[mt][nt][3] = b1v;
        }
    }
    __syncthreads();

    for (int kk = 0; kk < 25; kk++) {
        uint4 nb[4];
        if (kk < 24) {
            const char* bsrc = (const char*)g_q2b + (size_t)(kk + 1) * 128 * 128;
#pragma unroll
            for (int j = 0; j < 4; j++) {
                int i = tid + j * 256;
                int row = i >> 3, ch = i & 7;
                nb[j] = *(const uint4*)(bsrc + row * 128 + ch * 16);
            }
        }
        const char* bb = Bsm + (kk & 1) * CV2_BBYTES;
        const int dby = ((kk / 5) * 12 + (kk % 5)) * 272;   // spatial shift
#pragma unroll
        for (int kstep = 0; kstep < 8; kstep++) {
            const int acb = kstep * 32;           // A col byte base
            const int c0 = 2 * (kstep & 3);       // B chunk base (hi/lo reuse)
            unsigned a[2][4];
#pragma unroll
            for (int mt = 0; mt < 2; mt++) {
                const char* p0 = Xs + abase[mt][0] + dby + acb;
                const char* p1 = Xs + abase[mt][1] + dby + acb;
                a[mt][0] = *(const unsigned*)p0;
                a[mt][1] = *(const unsigned*)p1;
                a[mt][2] = *(const unsigned*)(p0 + 16);
                a[mt][3] = *(const unsigned*)(p1 + 16);
            }
#pragma unroll
            for (int nt = 0; nt < 8; nt++) {
                int n = n0w + nt * 8 + g;
                const char* brow = bb + n * 128;
                unsigned b0 = *(const unsigned*)(brow + ((c0 ^ (n & 7)) << 4) + 4 * t);
                unsigned b1 = *(const unsigned*)(brow + (((c0 + 1) ^ (n & 7)) << 4) + 4 * t);
#pragma unroll
                for (int mt = 0; mt < 2; mt++) {
                    asm volatile(
                        "mma.sync.aligned.m16n8k16.row.col.f32.f16.f16.f32 "
                        "{%0,%1,%2,%3}, {%4,%5,%6,%7}, {%8,%9}, {%0,%1,%2,%3};"
                        : "+f"(acc[mt][nt][0]), "+f"(acc[mt][nt][1]),
                          "+f"(acc[mt][nt][2]), "+f"(acc[mt][nt][3])
                        : "r"(a[mt][0]), "r"(a[mt][1]), "r"(a[mt][2]), "r"(a[mt][3]),
                          "r"(b0), "r"(b1));
                }
            }
        }
        if (kk < 24) {
            char* bw = Bsm + ((kk + 1) & 1) * CV2_BBYTES;
#pragma unroll
            for (int j = 0; j < 4; j++) {
                int i = tid + j * 256;
                int row = i >> 3, ch = i & 7;
                *(uint4*)(bw + row * 128 + ((ch ^ (row & 7)) << 4)) = nb[j];
            }
        }
        __syncthreads();
    }

    // epilogue -> g_c2n [b][s64][oc] NHWC
#pragma unroll
    for (int mt = 0; mt < 2; mt++)
#pragma unroll
        for (int rr = 0; rr < 2; rr++) {
            int m = m0w + mt * 16 + g + rr * 8;
            int img = m >> 6, sp = m & 63;
            size_t base = ((size_t)(blk * 2 + img) * 64 + sp) * 128;
#pragma unroll
            for (int nt = 0; nt < 8; nt++) {
                int n = n0w + nt * 8 + 2 * t;
                *(float2*)&g_c2n[base + n] =
                    make_float2(acc[mt][nt][2 * rr], acc[mt][nt][2 * rr + 1]);
            }
        }
}

// ------------- pool2: NHWC conv2 out -> NCHW-flat [b][oc*16+y*4+x] ----------
__global__ void k_pool2n() {
    int b = blockIdx.x, t = threadIdx.x;  // t = oc (128)
    float a = g_sc2[t], sh = g_sh2[t];
    const float* src = &g_c2n[(size_t)b * 64 * 128];
#pragma unroll
    for (int p = 0; p < 16; p++) {
        int y = p >> 2, x = p & 3;
        int s0 = (2 * y) * 8 + 2 * x;
        float v00 = src[(size_t)s0 * 128 + t];
        float v01 = src[(size_t)(s0 + 1) * 128 + t];
        float v10 = src[(size_t)(s0 + 8) * 128 + t];
        float v11 = src[(size_t)(s0 + 9) * 128 + t];
        float r0 = fmaxf(fmaf(a, v00, sh), fmaf(a, v01, sh));
        float r1 = fmaxf(fmaf(a, v10, sh), fmaf(a, v11, sh));
        g_p2[(size_t)b * FLAT + t * 16 + p] = fmaxf(fmaxf(r0, r1), 0.0f);
    }
}

// -------------------------------- fc1 (f32x2) -------------------------------
#define BM 64
#define BN 32
#define BK 32
__global__ void __launch_bounds__(128) k_fc1(const float* __restrict__ bias) {
    __shared__ __align__(16) float As[BK][BM];
    __shared__ __align__(16) float Wsh[BK][BN];
    int tid = threadIdx.x;
    int tx = tid & 7, ty = tid >> 3;
    int m0 = blockIdx.y * BM, f0 = blockIdx.x * BN;

    u64 acc[4][2];
#pragma unroll
    for (int i = 0; i < 4; i++) { acc[i][0] = 0ull; acc[i][1] = 0ull; }

    for (int kt = 0; kt < FLAT; kt += BK) {
        __syncthreads();
        for (int i = tid; i < BM * (BK / 4); i += 128) {
            int r = i >> 3, c4 = (i & 7) * 4;
            float4 v = *(const float4*)&g_p2[(size_t)(m0 + r) * FLAT + kt + c4];
            As[c4 + 0][r] = v.x; As[c4 + 1][r] = v.y;
            As[c4 + 2][r] = v.z; As[c4 + 3][r] = v.w;
        }
        for (int i = tid; i < BN * (BK / 4); i += 128) {
            int r = i >> 3, c4 = (i & 7) * 4;
            float4 v = *(const float4*)&g_qf1[(size_t)(f0 + r) * FLAT + kt + c4];
            Wsh[c4 + 0][r] = v.x; Wsh[c4 + 1][r] = v.y;
            Wsh[c4 + 2][r] = v.z; Wsh[c4 + 3][r] = v.w;
        }
        __syncthreads();
#pragma unroll
        for (int kk = 0; kk < BK; kk++) {
            float4 av = *(const float4*)&As[kk][ty * 4];
            u64 w0 = *(const u64*)&Wsh[kk][tx * 4];
            u64 w1 = *(const u64*)&Wsh[kk][tx * 4 + 2];
            float a[4] = {av.x, av.y, av.z, av.w};
#pragma unroll
            for (int i = 0; i < 4; i++) {
                u64 pa = pk2(a[i], a[i]);
                acc[i][0] = f2fma(pa, w0, acc[i][0]);
                acc[i][1] = f2fma(pa, w1, acc[i][1]);
            }
        }
    }
#pragma unroll
    for (int i = 0; i < 4; i++)
#pragma unroll
        for (int jp = 0; jp < 2; jp++) {
            float lo, hi;
            upk2(lo, hi, acc[i][jp]);
            int bb = m0 + ty * 4 + i, f = f0 + tx * 4 + 2 * jp;
            g_f1[(size_t)bb * F1 + f]     = lo + __ldg(&bias[f]);
            g_f1[(size_t)bb * F1 + f + 1] = hi + __ldg(&bias[f + 1]);
        }
}

// -------------------------------- fc2 --------------------------------------
__global__ void k_fc2(const float* __restrict__ bias, float* __restrict__ out) {
    int i = blockIdx.x * blockDim.x + threadIdx.x;
    if (i >= Bn * 10) return;
    int b = i / 10, j = i - b * 10;
    float s = __ldg(&bias[j]);
    const float* row = &g_f1[(size_t)b * F1];
    const float* w = &g_qf2[(size_t)j * F1];
    for (int f = 0; f < F1; f++) {
        float hh = fmaxf(fmaf(g_sc3[f], row[f], g_sh3[f]), 0.0f);
        s = fmaf(hh, w[f], s);
    }
    out[i] = s;
}

// ------------------------------ launcher -----------------------------------
extern "C" void kernel_launch(void* const* d_in, const int* in_sizes, int n_in,
                              void* d_out, int out_size) {
    const float* x    = (const float*)d_in[0];
    const float* c1w  = (const float*)d_in[1];
    const float* c1b  = (const float*)d_in[2];
    const float* bn1g = (const float*)d_in[3];
    const float* bn1b = (const float*)d_in[4];
    const float* c2w  = (const float*)d_in[5];
    const float* c2b  = (const float*)d_in[6];
    const float* bn2g = (const float*)d_in[7];
    const float* bn2b = (const float*)d_in[8];
    const float* f1w  = (const float*)d_in[9];
    const float* f1b  = (const float*)d_in[10];
    const float* bn3g = (const float*)d_in[11];
    const float* bn3b = (const float*)d_in[12];
    const float* f2w  = (const float*)d_in[13];
    const float* f2b  = (const float*)d_in[14];
    float* out = (float*)d_out;

    cudaFuncSetAttribute(k_conv2m, cudaFuncAttributeMaxDynamicSharedMemorySize,
                         CV2_SMEM);

    k_init<<<1, 1024>>>();

    k_absmax<<<2, 256>>>(c1w, C1 * 25 / 4, 0);
    k_absmax<<<200, 256>>>(c2w, C2 * C1 * 25 / 4, 1);
    k_absmax<<<1024, 256>>>(f1w, F1 * FLAT / 4, 2);
    k_absmax<<<5, 256>>>(f2w, 10 * F1 / 4, 3);

    k_quant1t<<<(C1 * 25 + 255) / 256, 256>>>(c1w);
    k_quant2b<<<(C2 * C1 * 25 + 255) / 256, 256>>>(c2w);
    k_quant3<<<2048, 256>>>(f1w);
    k_quant4<<<20, 256>>>(f2w);

    k_conv1<<<512, 288>>>(x, c1b);
    k_stats1<<<dim3(C1, 16), 256>>>();
    k_bnf1<<<1, 64>>>(bn1g, bn1b);
    k_pool1h<<<512, 256>>>();

    k_conv2m<<<256, 256, CV2_SMEM>>>(c2b);
    k_stats2n<<<128, 128>>>();
    k_bnf2<<<1, 128>>>(bn2g, bn2b);
    k_pool2n<<<512, 128>>>();

    k_fc1<<<dim3(F1 / BN, Bn / BM), 128>>>(f1b);
    k_stats3<<<F1, 256>>>();
    k_bnf3<<<2, 256>>>(bn3g, bn3b);

    k_fc2<<<20, 256>>>(f2b, out);
}